// round 6
// baseline (speedup 1.0000x reference)
#include <cuda_runtime.h>
#include <cstdint>

// ---------------- problem constants ----------------
#define NSEL   8
#define CIN    128
#define COUTC  128
#define HDIM   128
#define WDIM   128
#define HWP    16384            // HDIM*WDIM
#define NPIX   131072           // 8*HWP
#define KTOT   1152             // CIN*9
#define KC     32               // K per ktile
#define NKT    36               // KTOT/KC
#define PX_TILE 128
#define NBLK   512              // NPIX/256
#define INVALID_PIX 0xFFFFFFFFu

#define BFRAG_B 16384
#define SMEM_BYTES (2*BFRAG_B + 512)

// ---------------- scratch (static device; no allocs) ----------------
__device__ unsigned int  g_count[NSEL];
__device__ unsigned int  g_list[NSEL][NPIX];                    // 4 MB
__device__ unsigned char g_bs[NPIX];
__device__ unsigned int  g_bhist[NBLK][NSEL];
__device__ unsigned int  g_bbase[NBLK][NSEL];
__device__ __align__(16) unsigned int g_wb[NSEL * NKT * 4096];  // swizzled frag-record tf32 B tiles

// ---------------- PTX helpers ----------------
static __device__ __forceinline__ uint32_t smem_u32(const void* p) {
    uint32_t a;
    asm("{ .reg .u64 t; cvta.to.shared.u64 t, %1; cvt.u32.u64 %0, t; }" : "=r"(a) : "l"(p));
    return a;
}
static __device__ __forceinline__ uint32_t f2tf32(float v) {
    uint32_t u; asm("cvt.rna.tf32.f32 %0, %1;" : "=r"(u) : "f"(v)); return u;
}
#define CP_ASYNC16(dst, src) \
    asm volatile("cp.async.cg.shared.global [%0], [%1], 16;" :: "r"(dst), "l"(src))
#define CP_COMMIT() asm volatile("cp.async.commit_group;" ::: "memory")
#define CP_WAIT0()  asm volatile("cp.async.wait_group 0;" ::: "memory")

#define LDS128(v, addr) \
    asm volatile("ld.shared.v4.b32 {%0,%1,%2,%3}, [%4];" \
        : "=r"((v)[0]), "=r"((v)[1]), "=r"((v)[2]), "=r"((v)[3]) : "r"(addr))

static __device__ __forceinline__ void mma_tf32(float c[4], uint32_t a0, uint32_t a1,
                                                uint32_t a2, uint32_t a3,
                                                uint32_t b0, uint32_t b1) {
    asm volatile(
        "mma.sync.aligned.m16n8k8.row.col.f32.tf32.tf32.f32 "
        "{%0,%1,%2,%3}, {%4,%5,%6,%7}, {%8,%9}, {%0,%1,%2,%3};"
        : "+f"(c[0]), "+f"(c[1]), "+f"(c[2]), "+f"(c[3])
        : "r"(a0), "r"(a1), "r"(a2), "r"(a3), "r"(b0), "r"(b1));
}

// ---------------------------------------------------------------------------
// Kernel 1: argmax gate + per-block histograms
// ---------------------------------------------------------------------------
__global__ void hist_kernel(const float* __restrict__ selector) {
    __shared__ unsigned int h[NSEL];
    int tid = threadIdx.x;
    if (tid < NSEL) h[tid] = 0u;
    __syncthreads();

    int p  = blockIdx.x * 256 + tid;
    int b  = p >> 14;
    int hw = p & (HWP - 1);
    const float* sp = selector + (size_t)b * NSEL * HWP + hw;
    float best = sp[0];
    int bs = 0;
#pragma unroll
    for (int s = 1; s < NSEL; s++) {
        float v = sp[(size_t)s * HWP];
        if (v > best) { best = v; bs = s; }
    }
    g_bs[p] = (unsigned char)bs;
    atomicAdd(&h[bs], 1u);
    __syncthreads();
    if (tid < NSEL) g_bhist[blockIdx.x][tid] = h[tid];
}

// ---------------------------------------------------------------------------
// Kernel 2: exclusive scan of block histograms per bin (1 CTA)
// ---------------------------------------------------------------------------
__global__ void scan_kernel() {
    __shared__ unsigned int part[NSEL][32];
    int tid = threadIdx.x;
    int s = tid & 7, c = tid >> 3;
    unsigned int sum = 0;
#pragma unroll
    for (int b = c * 16; b < c * 16 + 16; b++) sum += g_bhist[b][s];
    part[s][c] = sum;
    __syncthreads();
    if (tid < NSEL) {
        unsigned int run = 0;
#pragma unroll
        for (int c2 = 0; c2 < 32; c2++) {
            unsigned int t = part[tid][c2];
            part[tid][c2] = run;
            run += t;
        }
        g_count[tid] = run;
    }
    __syncthreads();
    unsigned int run = part[s][c];
    for (int b = c * 16; b < c * 16 + 16; b++) {
        g_bbase[b][s] = run;
        run += g_bhist[b][s];
    }
}

// ---------------------------------------------------------------------------
// Kernel 3: ordered scatter -> sorted per-bin pixel lists
// ---------------------------------------------------------------------------
__global__ void scatter_kernel() {
    __shared__ unsigned int wh[8][NSEL];
    int tid = threadIdx.x;
    int wid = tid >> 5;
    if (tid < 64) ((unsigned int*)wh)[tid] = 0u;
    __syncthreads();

    int p = blockIdx.x * 256 + tid;
    int bs = g_bs[p];
    unsigned int mask = __match_any_sync(0xFFFFFFFFu, bs);
    unsigned int lt   = (1u << (tid & 31)) - 1u;
    unsigned int rank = __popc(mask & lt);
    if (rank == 0) wh[wid][bs] = __popc(mask);
    __syncthreads();
    if (tid < NSEL) {
        unsigned int run = 0;
#pragma unroll
        for (int w = 0; w < 8; w++) {
            unsigned int t = wh[w][tid];
            wh[w][tid] = run;
            run += t;
        }
    }
    __syncthreads();
    unsigned int idx = g_bbase[blockIdx.x][bs] + wh[wid][bs] + rank;
    g_list[bs][idx] = (unsigned int)p;
}

// ---------------------------------------------------------------------------
// Kernel 4: weight repack -> swizzled fragment-record tf32 B tiles.
// Tile (s,kt): element e = (j*32+lane)*8 + t*2 + reg
//   co = j*8 + (lane>>2); kk = kt*32 + t*8 + (lane&3) + reg*4
// stored at byte addr (within tile): unit' = (e>>2) ^ (((e>>2)>>3)&7), unit'*16 + (e&3)*4
// ---------------------------------------------------------------------------
__global__ void reorg_kernel(const float* __restrict__ w) {
    int t = blockIdx.x * 256 + threadIdx.x;       // 8*36*4096 threads
    int e    = t & 4095;
    int tile = t >> 12;                           // s*36 + kt
    int kt = tile % NKT;
    int s  = tile / NKT;
    int reg  = e & 1;
    int tt   = (e >> 1) & 3;
    int lane = (e >> 3) & 31;
    int j    = e >> 8;
    int co = j * 8 + (lane >> 2);
    int kk = kt * 32 + tt * 8 + (lane & 3) + reg * 4;
    int ci = kk / 9;
    int r  = kk - ci * 9;
    float v = w[(((size_t)co * CIN + ci) * NSEL + s) * 9 + r];
    uint32_t unit = (uint32_t)(e >> 2);
    unit ^= (unit >> 3) & 7u;
    *(uint32_t*)((char*)(g_wb + (size_t)tile * 4096) + unit * 16u + (e & 3) * 4u) = f2tf32(v);
}

// ---------------------------------------------------------------------------
// Kernel 5: grouped implicit-GEMM conv, tf32 mma.sync.
//   8 warps = 8 M-slices of 16 px, full N=128 per warp.
//   A: direct LDG->cvt->fragment registers (prefetched 1 ktile ahead).
//   B: double-buffered smem fragment records, 2x LDS128 per (j,ktile).
// ---------------------------------------------------------------------------
__global__ void __launch_bounds__(256, 2)
conv_kernel(const float* __restrict__ input,
            const float* __restrict__ bias,
            float* __restrict__ out) {
    const int s = blockIdx.y;
    const unsigned int cnt = g_count[s];
    const int tile0 = blockIdx.x * PX_TILE;
    if (tile0 >= (int)cnt) return;

    extern __shared__ char dsm[];
    const uint32_t Bbase = smem_u32(dsm);
    unsigned int* spix = (unsigned int*)(dsm + 2 * BFRAG_B);

    const int tid  = threadIdx.x;
    const int wid  = tid >> 5;
    const int lane = tid & 31;

    if (tid < PX_TILE) {
        int idx = tile0 + tid;
        spix[tid] = (idx < (int)cnt) ? g_list[s][idx] : INVALID_PIX;
    }
    __syncthreads();

    const int rr = lane >> 2;
    const int kq = lane & 3;
    const unsigned int p0 = spix[wid * 16 + rr];
    const unsigned int p1 = spix[wid * 16 + rr + 8];
    const bool v0 = (p0 != INVALID_PIX);
    const bool v1 = (p1 != INVALID_PIX);
    const int gh0 = (p0 >> 7) & 127, gw0 = p0 & 127;
    const int gh1 = (p1 >> 7) & 127, gw1 = p1 & 127;
    const float* cb0 = input + ((size_t)(p0 >> 14) * CIN) * HWP + gh0 * WDIM + gw0;
    const float* cb1 = input + ((size_t)(p1 >> 14) * CIN) * HWP + gh1 * WDIM + gw1;
    const bool fast01 = v0 && v1 &&
        gh0 >= 1 && gh0 <= 126 && gw0 >= 1 && gw0 <= 126 &&
        gh1 >= 1 && gh1 <= 126 && gw1 >= 1 && gw1 <= 126;

    // B LDS addressing (swizzle folds to constant XOR of rr<<4)
    const uint32_t off0 = (uint32_t)(lane * 32)      ^ ((uint32_t)rr << 4);
    const uint32_t off1 = (uint32_t)(lane * 32 + 16) ^ ((uint32_t)rr << 4);

    float acc[16][4];
#pragma unroll
    for (int j = 0; j < 16; j++)
#pragma unroll
        for (int e = 0; e < 4; e++) acc[j][e] = 0.f;

    const unsigned int* wtiles = g_wb + (size_t)s * NKT * 4096;

    // ---- A gather: 8 taps (kq+4m) x 2 px rows for ktile kt ----
    auto gather = [&](int kt, uint32_t* d0, uint32_t* d1) {
        int kk0 = kt * KC + kq;
        int ci = kk0 / 9;
        int r  = kk0 - ci * 9;
        if (fast01) {
#pragma unroll
            for (int m = 0; m < 8; m++) {
                int kh = (r * 11) >> 5;
                int kw = r - kh * 3;
                int off = ci * HWP + (kh - 1) * WDIM + (kw - 1);
                d0[m] = __float_as_uint(__ldg(cb0 + off));
                d1[m] = __float_as_uint(__ldg(cb1 + off));
                r += 4; if (r >= 9) { r -= 9; ci++; }
            }
        } else {
#pragma unroll
            for (int m = 0; m < 8; m++) {
                int kh = (r * 11) >> 5;
                int kw = r - kh * 3;
                int off = ci * HWP + (kh - 1) * WDIM + (kw - 1);
                float f0 = 0.f, f1 = 0.f;
                int y0 = gh0 + kh - 1, x0 = gw0 + kw - 1;
                int y1 = gh1 + kh - 1, x1 = gw1 + kw - 1;
                if (v0 && (unsigned)y0 < 128u && (unsigned)x0 < 128u) f0 = __ldg(cb0 + off);
                if (v1 && (unsigned)y1 < 128u && (unsigned)x1 < 128u) f1 = __ldg(cb1 + off);
                d0[m] = __float_as_uint(f0);
                d1[m] = __float_as_uint(f1);
                r += 4; if (r >= 9) { r -= 9; ci++; }
            }
        }
    };

    auto cvt8 = [&](uint32_t* d) {
#pragma unroll
        for (int m = 0; m < 8; m++) d[m] = f2tf32(__uint_as_float(d[m]));
    };

    auto fillB = [&](int kt, int buf) {
        const char* src = (const char*)(wtiles + (size_t)kt * 4096);
        const uint32_t dst = Bbase + buf * BFRAG_B;
#pragma unroll
        for (int i = 0; i < 4; i++)
            CP_ASYNC16(dst + (tid + 256 * i) * 16u, src + (tid + 256 * i) * 16);
    };

    auto compute = [&](const uint32_t* c0, const uint32_t* c1, uint32_t Bb) {
#pragma unroll
        for (int j = 0; j < 16; j++) {
            uint32_t b[8];
            LDS128(b,     Bb + (uint32_t)(j * 1024) + off0);
            LDS128(b + 4, Bb + (uint32_t)(j * 1024) + off1);
#pragma unroll
            for (int t = 0; t < 4; t++)
                mma_tf32(acc[j], c0[2 * t], c1[2 * t], c0[2 * t + 1], c1[2 * t + 1],
                         b[2 * t], b[2 * t + 1]);
        }
    };

    uint32_t sA0[8], sA1[8], sB0[8], sB1[8];

    // ---------- prologue ----------
    fillB(0, 0);
    CP_COMMIT();
    gather(0, sA0, sA1);
    CP_WAIT0();
    __syncthreads();

    // ---------- main loop (ping-pong stages, 2 ktiles per trip) ----------
#pragma unroll 1
    for (int kt = 0; kt < NKT; kt += 2) {
        // even ktile: consume stage A / buf0, prefetch stage B / buf1
        fillB(kt + 1, 1);
        CP_COMMIT();
        gather(kt + 1, sB0, sB1);
        cvt8(sA0); cvt8(sA1);
        compute(sA0, sA1, Bbase);
        CP_WAIT0();
        __syncthreads();

        // odd ktile: consume stage B / buf1, prefetch stage A / buf0
        const bool more = (kt + 2 < NKT);
        if (more) {
            fillB(kt + 2, 0);
            CP_COMMIT();
            gather(kt + 2, sA0, sA1);
        }
        cvt8(sB0); cvt8(sB1);
        compute(sB0, sB1, Bbase + BFRAG_B);
        if (more) CP_WAIT0();
        __syncthreads();
    }

    // ---------- epilogue: bias + scattered stores ----------
    const int co0 = kq * 2;
    float bvr[16][2];
#pragma unroll
    for (int j = 0; j < 16; j++) {
        bvr[j][0] = __ldg(&bias[j * 8 + co0]);
        bvr[j][1] = __ldg(&bias[j * 8 + co0 + 1]);
    }
    if (v0) {
        float* ob = out + ((size_t)(p0 >> 14) * COUTC) * HWP + (p0 & (HWP - 1));
#pragma unroll
        for (int j = 0; j < 16; j++) {
            const int co = j * 8 + co0;
            ob[(size_t)co * HWP]       = acc[j][0] + bvr[j][0];
            ob[(size_t)(co + 1) * HWP] = acc[j][1] + bvr[j][1];
        }
    }
    if (v1) {
        float* ob = out + ((size_t)(p1 >> 14) * COUTC) * HWP + (p1 & (HWP - 1));
#pragma unroll
        for (int j = 0; j < 16; j++) {
            const int co = j * 8 + co0;
            ob[(size_t)co * HWP]       = acc[j][2] + bvr[j][0];
            ob[(size_t)(co + 1) * HWP] = acc[j][3] + bvr[j][1];
        }
    }
}

// ---------------------------------------------------------------------------
extern "C" void kernel_launch(void* const* d_in, const int* in_sizes, int n_in,
                              void* d_out, int out_size) {
    const float* input    = (const float*)d_in[0];   // [8,128,128,128]
    const float* selector = (const float*)d_in[1];   // [8,8,128,128]
    const float* weight   = (const float*)d_in[2];   // [128,128,8,3,3]
    const float* bias     = (const float*)d_in[3];   // [128]
    float* out = (float*)d_out;                      // [8,128,128,128]

    hist_kernel<<<NBLK, 256>>>(selector);
    scan_kernel<<<1, 256>>>();
    scatter_kernel<<<NBLK, 256>>>();
    reorg_kernel<<<(NSEL * NKT * 4096) / 256, 256>>>(weight);
    conv_kernel<<<dim3(NPIX / PX_TILE, NSEL), 256, SMEM_BYTES>>>(input, bias, out);
}

// round 8
// speedup vs baseline: 1.1692x; 1.1692x over previous
#include <cuda_runtime.h>
#include <cstdint>

// ---------------- problem constants ----------------
#define NSEL   8
#define CIN    128
#define COUTC  128
#define HDIM   128
#define WDIM   128
#define HWP    16384            // HDIM*WDIM
#define NPIX   131072           // 8*HWP
#define NELEM  (NPIX * CIN)     // 16,777,216 input elements
#define KTOT   1152             // CIN*9
#define KC     32               // K per ktile
#define NKT    36               // KTOT/KC
#define PX_TILE 128
#define NBLK   512              // NPIX/256
#define INVALID_PIX 0xFFFFFFFFu

#define AFRAG_B 16384
#define BFRAG_B 16384
#define SMEM_BYTES (2*AFRAG_B + 2*BFRAG_B + 512)

// ---------------- scratch (static device; no allocs) ----------------
__device__ unsigned int  g_count[NSEL];
__device__ unsigned int  g_list[NSEL][NPIX];                    // 4 MB
__device__ unsigned char g_bs[NPIX];
__device__ unsigned int  g_bhist[NBLK][NSEL];
__device__ unsigned int  g_bbase[NBLK][NSEL];
__device__ __align__(16) unsigned int g_wb[NSEL * NKT * 4096];  // frag-record tf32 B tiles
__device__ __align__(16) float g_in[NELEM];                     // 64 MB tf32-rounded input

// ---------------- PTX helpers ----------------
static __device__ __forceinline__ uint32_t smem_u32(const void* p) {
    uint32_t a;
    asm("{ .reg .u64 t; cvta.to.shared.u64 t, %1; cvt.u32.u64 %0, t; }" : "=r"(a) : "l"(p));
    return a;
}
static __device__ __forceinline__ uint32_t f2tf32(float v) {
    uint32_t u; asm("cvt.rna.tf32.f32 %0, %1;" : "=r"(u) : "f"(v)); return u;
}
#define CP_ASYNC16(dst, src) \
    asm volatile("cp.async.cg.shared.global [%0], [%1], 16;" :: "r"(dst), "l"(src))
#define CP_ASYNC4(dst, src) \
    asm volatile("cp.async.ca.shared.global [%0], [%1], 4;" :: "r"(dst), "l"(src))
#define CP_ASYNC4Z(dst, src, sz) \
    asm volatile("cp.async.ca.shared.global [%0], [%1], 4, %2;" :: "r"(dst), "l"(src), "r"(sz))
#define CP_COMMIT() asm volatile("cp.async.commit_group;" ::: "memory")
#define CP_WAIT0()  asm volatile("cp.async.wait_group 0;" ::: "memory")

#define LDS128(v, addr) \
    asm volatile("ld.shared.v4.b32 {%0,%1,%2,%3}, [%4];" \
        : "=r"((v)[0]), "=r"((v)[1]), "=r"((v)[2]), "=r"((v)[3]) : "r"(addr))
#define LDS64(v, addr) \
    asm volatile("ld.shared.v2.b32 {%0,%1}, [%2];" \
        : "=r"((v)[0]), "=r"((v)[1]) : "r"(addr))

static __device__ __forceinline__ void mma_tf32(float c[4], uint32_t a0, uint32_t a1,
                                                uint32_t a2, uint32_t a3,
                                                uint32_t b0, uint32_t b1) {
    asm volatile(
        "mma.sync.aligned.m16n8k8.row.col.f32.tf32.tf32.f32 "
        "{%0,%1,%2,%3}, {%4,%5,%6,%7}, {%8,%9}, {%0,%1,%2,%3};"
        : "+f"(c[0]), "+f"(c[1]), "+f"(c[2]), "+f"(c[3])
        : "r"(a0), "r"(a1), "r"(a2), "r"(a3), "r"(b0), "r"(b1));
}

// ---------------------------------------------------------------------------
// Kernel 0: round input to tf32 grid (rna) once -> g_in.
// MMA truncation of these values is then exact (bitwise same math as R4).
// ---------------------------------------------------------------------------
__global__ void round_kernel(const float4* __restrict__ in) {
    int t = blockIdx.x * 256 + threadIdx.x;      // NELEM/4 threads
    float4 v = in[t];
    uint4 o;
    o.x = f2tf32(v.x); o.y = f2tf32(v.y); o.z = f2tf32(v.z); o.w = f2tf32(v.w);
    reinterpret_cast<uint4*>(g_in)[t] = o;
}

// ---------------------------------------------------------------------------
// Kernel 1: argmax gate + per-block histograms
// ---------------------------------------------------------------------------
__global__ void hist_kernel(const float* __restrict__ selector) {
    __shared__ unsigned int h[NSEL];
    int tid = threadIdx.x;
    if (tid < NSEL) h[tid] = 0u;
    __syncthreads();

    int p  = blockIdx.x * 256 + tid;
    int b  = p >> 14;
    int hw = p & (HWP - 1);
    const float* sp = selector + (size_t)b * NSEL * HWP + hw;
    float best = sp[0];
    int bs = 0;
#pragma unroll
    for (int s = 1; s < NSEL; s++) {
        float v = sp[(size_t)s * HWP];
        if (v > best) { best = v; bs = s; }
    }
    g_bs[p] = (unsigned char)bs;
    atomicAdd(&h[bs], 1u);
    __syncthreads();
    if (tid < NSEL) g_bhist[blockIdx.x][tid] = h[tid];
}

// ---------------------------------------------------------------------------
// Kernel 2: exclusive scan of block histograms per bin (1 CTA)
// ---------------------------------------------------------------------------
__global__ void scan_kernel() {
    __shared__ unsigned int part[NSEL][32];
    int tid = threadIdx.x;
    int s = tid & 7, c = tid >> 3;
    unsigned int sum = 0;
#pragma unroll
    for (int b = c * 16; b < c * 16 + 16; b++) sum += g_bhist[b][s];
    part[s][c] = sum;
    __syncthreads();
    if (tid < NSEL) {
        unsigned int run = 0;
#pragma unroll
        for (int c2 = 0; c2 < 32; c2++) {
            unsigned int t = part[tid][c2];
            part[tid][c2] = run;
            run += t;
        }
        g_count[tid] = run;
    }
    __syncthreads();
    unsigned int run = part[s][c];
    for (int b = c * 16; b < c * 16 + 16; b++) {
        g_bbase[b][s] = run;
        run += g_bhist[b][s];
    }
}

// ---------------------------------------------------------------------------
// Kernel 3: ordered scatter -> sorted per-bin pixel lists
// ---------------------------------------------------------------------------
__global__ void scatter_kernel() {
    __shared__ unsigned int wh[8][NSEL];
    int tid = threadIdx.x;
    int wid = tid >> 5;
    if (tid < 64) ((unsigned int*)wh)[tid] = 0u;
    __syncthreads();

    int p = blockIdx.x * 256 + tid;
    int bs = g_bs[p];
    unsigned int mask = __match_any_sync(0xFFFFFFFFu, bs);
    unsigned int lt   = (1u << (tid & 31)) - 1u;
    unsigned int rank = __popc(mask & lt);
    if (rank == 0) wh[wid][bs] = __popc(mask);
    __syncthreads();
    if (tid < NSEL) {
        unsigned int run = 0;
#pragma unroll
        for (int w = 0; w < 8; w++) {
            unsigned int t = wh[w][tid];
            wh[w][tid] = run;
            run += t;
        }
    }
    __syncthreads();
    unsigned int idx = g_bbase[blockIdx.x][bs] + wh[wid][bs] + rank;
    g_list[bs][idx] = (unsigned int)p;
}

// ---------------------------------------------------------------------------
// Kernel 4: weight repack -> fragment-order tf32 B tiles (same as R4).
// Tile (s,kt) element e = ((j*4+t)*32 + lane)*2 + reg
//   co = j*8 + (lane>>2); kk = kt*32 + t*8 + reg*4 + (lane&3)
// ---------------------------------------------------------------------------
__global__ void reorg_kernel(const float* __restrict__ w) {
    int t = blockIdx.x * 256 + threadIdx.x;       // 8*36*4096 threads
    int e    = t & 4095;
    int tile = t >> 12;                           // s*36 + kt
    int kt = tile % NKT;
    int s  = tile / NKT;
    int reg  = e & 1;
    int lane = (e >> 1) & 31;
    int tt   = (e >> 6) & 3;
    int j    = e >> 8;
    int co = j * 8 + (lane >> 2);
    int kk = kt * 32 + tt * 8 + reg * 4 + (lane & 3);
    int ci = kk / 9;
    int r  = kk - ci * 9;
    g_wb[t] = f2tf32(w[(((size_t)co * CIN + ci) * NSEL + s) * 9 + r]);
}

// ---------------------------------------------------------------------------
// Kernel 5: grouped implicit-GEMM conv, tf32 mma.sync, async A-gather.
//   8 warps = 2(M) x 4(N): warp tile 64px x 32co, K=1152 in 36 chunks of 32.
//   A: 16x cp.async.ca 4B per thread directly into frag-record smem slots
//      (input pre-rounded to tf32 grid by round_kernel; MMA truncation exact).
//   B: cp.async 16B bulk copy of frag-order tiles. Double-buffered both.
// ---------------------------------------------------------------------------
__global__ void __launch_bounds__(256, 2)
conv_kernel(const float* __restrict__ bias, float* __restrict__ out) {
    const int s = blockIdx.y;
    const unsigned int cnt = g_count[s];
    const int tile0 = blockIdx.x * PX_TILE;
    if (tile0 >= (int)cnt) return;

    extern __shared__ char dsm[];
    const uint32_t Abase = smem_u32(dsm);
    const uint32_t Bbase = Abase + 2 * AFRAG_B;
    unsigned int* spix = (unsigned int*)(dsm + 2 * AFRAG_B + 2 * BFRAG_B);

    const int tid  = threadIdx.x;
    const int wid  = tid >> 5;
    const int lane = tid & 31;

    if (tid < PX_TILE) {
        int idx = tile0 + tid;
        spix[tid] = (idx < (int)cnt) ? g_list[s][idx] : INVALID_PIX;
    }
    __syncthreads();

    // ---- gather assignment: px = tid>>1, K half kg = tid&1 (16 taps each) ----
    const int gpx = tid >> 1;
    const int kg  = tid & 1;
    const unsigned int gp = spix[gpx];
    const bool gvalid = (gp != INVALID_PIX);
    const int gh = (gp >> 7) & 127, gw = gp & 127;
    const float* cbase = gvalid
        ? g_in + ((size_t)(gp >> 14) * CIN) * HWP + gh * WDIM + gw
        : g_in;                                    // safe pointer for src-size=0
    const bool fast = gvalid && gh >= 1 && gh <= 126 && gw >= 1 && gw <= 126;

    // A-record destination constants:
    //   block = (i_px*4 + t_abs), 512B each; slot' = ((gpx&7)*4+kq) ^ swz; hoff px>=8
    const int i_px = gpx >> 4;
    const uint32_t hoff = ((gpx >> 3) & 1) * 8;
    uint32_t slotoff[4];
#pragma unroll
    for (int kq = 0; kq < 4; kq++) {
        uint32_t slot = (uint32_t)((gpx & 7) * 4 + kq);
        slot ^= (slot >> 3) & 3u;
        slotoff[kq] = slot * 16u + hoff;
    }
    const uint32_t AdstT0 = (uint32_t)((i_px * 4 + kg * 2) * 512);

    // ---- compute assignment: 8 warps = 2(M) x 4(N) ----
    const int wm = wid & 1;
    const int wn = wid >> 1;
    const uint32_t slotr = (uint32_t)lane ^ (((uint32_t)lane >> 3) & 3u);

    float acc[4][4][4];
#pragma unroll
    for (int i = 0; i < 4; i++)
#pragma unroll
        for (int j = 0; j < 4; j++)
#pragma unroll
            for (int e = 0; e < 4; e++) acc[i][j][e] = 0.f;

    const unsigned int* wtiles = g_wb + (size_t)s * NKT * 4096;

    // ---- A fill: 16 cp.async 4B (taps kt*32 + kg*16 + 0..15) ----
    auto fillA = [&](int kt, int buf) {
        const uint32_t db = Abase + buf * AFRAG_B + AdstT0;
        int kk0 = kt * KC + kg * 16;
        int ci = kk0 / 9;
        int r  = kk0 - ci * 9;
        int kh = (r * 11) >> 5;
        int kw = r - kh * 3;
        if (fast) {
            const float* ptr = cbase + ci * HWP + (kh - 1) * WDIM + (kw - 1);
#pragma unroll
            for (int j = 0; j < 16; j++) {
                uint32_t dst = db + (uint32_t)((j >> 3) * 512) + slotoff[j & 3] +
                               (uint32_t)(((j >> 2) & 1) * 4);
                CP_ASYNC4(dst, ptr);
                kw++; ptr++;
                if (kw == 3) {
                    kw = 0; kh++; ptr += WDIM - 3;
                    if (kh == 3) { kh = 0; ci++; ptr += HWP - 3 * WDIM; }
                }
            }
        } else {
#pragma unroll
            for (int j = 0; j < 16; j++) {
                int y = gh + kh - 1, x = gw + kw - 1;
                unsigned int sz =
                    (gvalid && (unsigned)y < 128u && (unsigned)x < 128u) ? 4u : 0u;
                const float* ptr = gvalid ? cbase + ci * HWP + (kh - 1) * WDIM + (kw - 1)
                                          : cbase;
                uint32_t dst = db + (uint32_t)((j >> 3) * 512) + slotoff[j & 3] +
                               (uint32_t)(((j >> 2) & 1) * 4);
                CP_ASYNC4Z(dst, ptr, sz);
                kw++;
                if (kw == 3) { kw = 0; kh++; if (kh == 3) { kh = 0; ci++; } }
            }
        }
    };

    auto fillB = [&](int kt, int buf) {
        const char* src = (const char*)(wtiles + (size_t)kt * 4096);
        const uint32_t dst = Bbase + buf * BFRAG_B;
#pragma unroll
        for (int i = 0; i < 4; i++)
            CP_ASYNC16(dst + (tid + 256 * i) * 16u, src + (tid + 256 * i) * 16);
    };

    // one k8 MMA step
    auto step = [&](int buf, int t) {
        const uint32_t Ab = Abase + buf * AFRAG_B;
        const uint32_t Bb = Bbase + buf * BFRAG_B;
        uint32_t av[4][4];
#pragma unroll
        for (int i = 0; i < 4; i++)
            LDS128(av[i], Ab + (uint32_t)((((wm * 4 + i) * 4 + t) * 32)) * 16u + slotr * 16u);
        uint32_t bv[4][2];
#pragma unroll
        for (int j = 0; j < 4; j++)
            LDS64(bv[j], Bb + (uint32_t)((((wn * 4 + j) * 4 + t) * 32 + lane)) * 8u);
#pragma unroll
        for (int j = 0; j < 4; j++)
#pragma unroll
            for (int i = 0; i < 4; i++)
                mma_tf32(acc[i][j], av[i][0], av[i][2], av[i][1], av[i][3],
                         bv[j][0], bv[j][1]);
    };

    // ---------- prologue ----------
    fillB(0, 0);
    fillA(0, 0);
    CP_COMMIT();
    CP_WAIT0();
    __syncthreads();

    // ---------- main loop ----------
#pragma unroll 1
    for (int kt = 0; kt < NKT; kt++) {
        const int cur = kt & 1, nxt = cur ^ 1;
        const bool more = (kt + 1 < NKT);
        if (more) {
            fillB(kt + 1, nxt);
            fillA(kt + 1, nxt);
            CP_COMMIT();
        }
        step(cur, 0);
        step(cur, 1);
        step(cur, 2);
        step(cur, 3);
        if (more) CP_WAIT0();
        __syncthreads();
    }

    // ---------- epilogue: bias + scattered stores ----------
    const int kq = lane & 3;
    float bv[4][2];
#pragma unroll
    for (int j = 0; j < 4; j++) {
        int co = wn * 32 + j * 8 + 2 * kq;
        bv[j][0] = __ldg(&bias[co]);
        bv[j][1] = __ldg(&bias[co + 1]);
    }
#pragma unroll
    for (int i = 0; i < 4; i++) {
        const int r0 = wm * 64 + i * 16 + (lane >> 2);
#pragma unroll
        for (int half = 0; half < 2; half++) {
            const unsigned int p = spix[r0 + half * 8];
            if (p == INVALID_PIX) continue;
            const int pb = p >> 14;
            const int hw = p & (HWP - 1);
            float* ob = out + ((size_t)pb * COUTC) * HWP + hw;
#pragma unroll
            for (int j = 0; j < 4; j++) {
                const int co = wn * 32 + j * 8 + 2 * kq;
                ob[(size_t)co * HWP]       = acc[i][j][half * 2]     + bv[j][0];
                ob[(size_t)(co + 1) * HWP] = acc[i][j][half * 2 + 1] + bv[j][1];
            }
        }
    }
}

// ---------------------------------------------------------------------------
extern "C" void kernel_launch(void* const* d_in, const int* in_sizes, int n_in,
                              void* d_out, int out_size) {
    const float* input    = (const float*)d_in[0];   // [8,128,128,128]
    const float* selector = (const float*)d_in[1];   // [8,8,128,128]
    const float* weight   = (const float*)d_in[2];   // [128,128,8,3,3]
    const float* bias     = (const float*)d_in[3];   // [128]
    float* out = (float*)d_out;                      // [8,128,128,128]

    static bool attr_done = false;
    if (!attr_done) {
        cudaFuncSetAttribute(conv_kernel, cudaFuncAttributeMaxDynamicSharedMemorySize, SMEM_BYTES);
        attr_done = true;
    }

    round_kernel<<<NELEM / 1024, 256>>>((const float4*)input);
    hist_kernel<<<NBLK, 256>>>(selector);
    scan_kernel<<<1, 256>>>();
    scatter_kernel<<<NBLK, 256>>>();
    reorg_kernel<<<(NSEL * NKT * 4096) / 256, 256>>>(weight);
    conv_kernel<<<dim3(NPIX / PX_TILE, NSEL), 256, SMEM_BYTES>>>(bias, out);
}